// round 2
// baseline (speedup 1.0000x reference)
#include <cuda_runtime.h>
#include <math.h>

#define B_ 8
#define C_ 384
#define H_ 96
#define W_ 96
#define GH_ 24
#define GW_ 24
#define G_ (GH_*GW_)   // 576

// Scratch (no allocations allowed)
__device__ __align__(16) float g_imp[B_ * H_ * W_];
__device__ __align__(16) float g_scores[B_ * G_];
__device__ int g_order[B_ * G_];

// ---------------------------------------------------------------------------
// Kernel A: fused dwconv3x3 + BN + SiLU + pointwise(C->1) + sigmoid
// grid (H_, B_), block (12, 32). Each thread: 8 w-outputs, 12 channels.
// ---------------------------------------------------------------------------
__global__ __launch_bounds__(384, 2)
void importance_kernel(const float* __restrict__ x,
                       const float* __restrict__ dw_w,
                       const float* __restrict__ bn_gamma,
                       const float* __restrict__ bn_beta,
                       const float* __restrict__ bn_mean,
                       const float* __restrict__ bn_var,
                       const float* __restrict__ pw_w,
                       const float* __restrict__ pw_b)
{
    __shared__ float sp[C_ * 12];       // per-channel: w0..w8 (scaled), shift, pw, pad
    __shared__ float spart[32][W_];     // per-channel-group partial logits

    const int tx = threadIdx.x;         // 0..11 : w-octet
    const int ty = threadIdx.y;         // 0..31 : channel group
    const int tid = ty * 12 + tx;       // 0..383

    // Prologue: fold BN scale into conv weights; one channel per thread.
    {
        const int c = tid;
        const float sc = bn_gamma[c] * rsqrtf(bn_var[c] + 1e-5f);
        #pragma unroll
        for (int k = 0; k < 9; ++k) sp[c * 12 + k] = dw_w[c * 9 + k] * sc;
        sp[c * 12 + 9]  = bn_beta[c] - bn_mean[c] * sc;
        sp[c * 12 + 10] = pw_w[c];
        sp[c * 12 + 11] = 0.f;
    }
    __syncthreads();

    const int h = blockIdx.x;
    const int b = blockIdx.y;
    const int w0 = tx * 8;
    const float* xb = x + ((size_t)b * C_) * (H_ * W_);

    float la[8];
    #pragma unroll
    for (int j = 0; j < 8; ++j) la[j] = 0.f;

    for (int cc = 0; cc < 12; ++cc) {
        const int c = ty * 12 + cc;
        const float4* pp = (const float4*)(sp + c * 12);
        const float4 p0 = pp[0];
        const float4 p1 = pp[1];
        const float4 p2 = pp[2];
        const float* xc = xb + c * (H_ * W_);

        float acc[8];
        #pragma unroll
        for (int j = 0; j < 8; ++j) acc[j] = p2.y;  // BN shift as init

        #pragma unroll
        for (int r = 0; r < 3; ++r) {
            const int hr = h + r - 1;
            float wk0, wk1, wk2;
            if (r == 0)      { wk0 = p0.x; wk1 = p0.y; wk2 = p0.z; }
            else if (r == 1) { wk0 = p0.w; wk1 = p1.x; wk2 = p1.y; }
            else             { wk0 = p1.z; wk1 = p1.w; wk2 = p2.x; }

            float win[10];
            if (hr >= 0 && hr < H_) {
                const float* row = xc + hr * W_ + w0;
                const float4 v0 = *(const float4*)row;
                const float4 v1 = *(const float4*)(row + 4);
                win[0] = (tx > 0)  ? row[-1] : 0.f;
                win[1] = v0.x; win[2] = v0.y; win[3] = v0.z; win[4] = v0.w;
                win[5] = v1.x; win[6] = v1.y; win[7] = v1.z; win[8] = v1.w;
                win[9] = (tx < 11) ? row[8] : 0.f;
            } else {
                #pragma unroll
                for (int k = 0; k < 10; ++k) win[k] = 0.f;
            }
            #pragma unroll
            for (int j = 0; j < 8; ++j)
                acc[j] += wk0 * win[j] + wk1 * win[j + 1] + wk2 * win[j + 2];
        }

        const float pw = p2.z;
        #pragma unroll
        for (int j = 0; j < 8; ++j) {
            const float hv = acc[j];
            // SiLU(h) * pw accumulated into logit. Precise expf for rank stability.
            const float s = 1.0f / (1.0f + expf(-hv));
            la[j] += (hv * s) * pw;
        }
    }

    #pragma unroll
    for (int j = 0; j < 8; ++j) spart[ty][w0 + j] = la[j];
    __syncthreads();

    if (tid < W_) {
        float s = 0.f;
        #pragma unroll 8
        for (int cg = 0; cg < 32; ++cg) s += spart[cg][tid];
        const float logit = s + pw_b[0];
        const float imp = 1.0f / (1.0f + expf(-logit));
        g_imp[(b * H_ + h) * W_ + tid] = imp;
    }
}

// ---------------------------------------------------------------------------
// Kernel B1: region scores = 4x4 block mean of importance. grid(B_), block(G_)
// ---------------------------------------------------------------------------
__global__ void scores_kernel()
{
    const int b = blockIdx.x;
    const int g = threadIdx.x;          // 0..575
    const int gh = g / GW_;
    const int gw = g - gh * GW_;
    const float4* ip = (const float4*)g_imp;
    float s = 0.f;
    #pragma unroll
    for (int rh = 0; rh < 4; ++rh) {
        const float4 v = ip[(b * H_ + gh * 4 + rh) * (W_ / 4) + gw];
        s += v.x + v.y + v.z + v.w;
    }
    g_scores[b * G_ + g] = s * (1.0f / 16.0f);
}

// ---------------------------------------------------------------------------
// Kernel B2: stable descending rank -> order. grid(9, B_), block(256).
// rank(g) = #{j: s_j > s_g} + #{j < g: s_j == s_g}; order[rank] = g.
// 4 lanes per g, each scans 144 of 576.
// ---------------------------------------------------------------------------
__global__ void rank_kernel()
{
    __shared__ float ssc[G_];
    const int b = blockIdx.y;
    const int tid = threadIdx.x;
    for (int i = tid; i < G_; i += 256) ssc[i] = g_scores[b * G_ + i];
    __syncthreads();

    const int sub = tid & 3;
    const int g = blockIdx.x * 64 + (tid >> 2);
    const float sg = ssc[g];
    int cnt = 0;
    const int j0 = sub * 144;
    #pragma unroll 4
    for (int j = j0; j < j0 + 144; ++j) {
        const float sj = ssc[j];
        cnt += (sj > sg) || (sj == sg && j < g);
    }
    cnt += __shfl_xor_sync(0xFFFFFFFFu, cnt, 1);
    cnt += __shfl_xor_sync(0xFFFFFFFFu, cnt, 2);
    if (sub == 0) g_order[b * G_ + cnt] = g;
}

// ---------------------------------------------------------------------------
// Kernel C: out[b,c, dstRegion, intra] = x[b,c, srcRegion, intra] * (1+gs*imp)
// grid (12, C_, B_), block (24, 8). One float4 (one 4-wide region row) / thread.
// ---------------------------------------------------------------------------
__global__ __launch_bounds__(192)
void permute_kernel(const float* __restrict__ x,
                    const float* __restrict__ gs_p,
                    float* __restrict__ out)
{
    const int w4 = threadIdx.x;                    // 0..23 == gw of dst
    const int h  = blockIdx.x * 8 + threadIdx.y;   // 0..95
    const int c  = blockIdx.y;
    const int b  = blockIdx.z;
    const int gh = h >> 2;
    const int rh = h & 3;

    const int src = g_order[b * G_ + gh * GW_ + w4];
    const int gh_s = src / GW_;
    const int gw_s = src - gh_s * GW_;
    const int h_s = gh_s * 4 + rh;

    const float4* xp = (const float4*)x;
    const float4 v = __ldg(&xp[(((size_t)b * C_ + c) * H_ + h_s) * (W_ / 4) + gw_s]);
    const float4* ip = (const float4*)g_imp;
    const float4 im = ip[(b * H_ + h_s) * (W_ / 4) + gw_s];
    const float gs = __ldg(gs_p);

    float4 o;
    o.x = v.x * fmaf(gs, im.x, 1.0f);
    o.y = v.y * fmaf(gs, im.y, 1.0f);
    o.z = v.z * fmaf(gs, im.z, 1.0f);
    o.w = v.w * fmaf(gs, im.w, 1.0f);
    ((float4*)out)[(((size_t)b * C_ + c) * H_ + h) * (W_ / 4) + w4] = o;
}

// ---------------------------------------------------------------------------
extern "C" void kernel_launch(void* const* d_in, const int* in_sizes, int n_in,
                              void* d_out, int out_size)
{
    const float* x        = (const float*)d_in[0];
    const float* dw_w     = (const float*)d_in[1];
    const float* bn_gamma = (const float*)d_in[2];
    const float* bn_beta  = (const float*)d_in[3];
    const float* bn_mean  = (const float*)d_in[4];
    const float* bn_var   = (const float*)d_in[5];
    const float* pw_w     = (const float*)d_in[6];
    const float* pw_b     = (const float*)d_in[7];
    const float* gs       = (const float*)d_in[8];
    float* out = (float*)d_out;

    importance_kernel<<<dim3(H_, B_), dim3(12, 32)>>>(
        x, dw_w, bn_gamma, bn_beta, bn_mean, bn_var, pw_w, pw_b);
    scores_kernel<<<B_, G_>>>();
    rank_kernel<<<dim3(9, B_), 256>>>();
    permute_kernel<<<dim3(12, C_, B_), dim3(24, 8)>>>(x, gs, out);
}

// round 5
// speedup vs baseline: 1.1571x; 1.1571x over previous
#include <cuda_runtime.h>
#include <math.h>

#define B_ 8
#define C_ 384
#define H_ 96
#define W_ 96
#define GH_ 24
#define GW_ 24
#define G_ (GH_*GW_)   // 576

// Scratch (no allocations allowed)
__device__ __align__(16) float g_imp[B_ * H_ * W_];
__device__ __align__(16) float g_scores[B_ * G_];
__device__ int g_order[B_ * G_];

// ---------------------------------------------------------------------------
// Kernel A: fused dwconv3x3 + BN + SiLU + pointwise(C->1) + sigmoid
// grid (H_, B_), block (24, 16). Each thread: 4 w-outputs, 24 channels.
// Fast-math SiLU (__expf/__fdividef); precise expf only for final sigmoid.
// ---------------------------------------------------------------------------
__global__ __launch_bounds__(384, 3)
void importance_kernel(const float* __restrict__ x,
                       const float* __restrict__ dw_w,
                       const float* __restrict__ bn_gamma,
                       const float* __restrict__ bn_beta,
                       const float* __restrict__ bn_mean,
                       const float* __restrict__ bn_var,
                       const float* __restrict__ pw_w,
                       const float* __restrict__ pw_b)
{
    __shared__ float sp[C_ * 12];       // per-channel: w0..w8 (BN-scaled), shift, pw, pad
    __shared__ float spart[16][W_];     // per-channel-group partial logits

    const int tx = threadIdx.x;         // 0..23 : w-quad
    const int ty = threadIdx.y;         // 0..15 : channel group (24 ch each)
    const int tid = ty * 24 + tx;       // 0..383

    // Prologue: fold BN scale into conv weights; one channel per thread.
    {
        const int c = tid;
        const float sc = bn_gamma[c] * rsqrtf(bn_var[c] + 1e-5f);
        #pragma unroll
        for (int k = 0; k < 9; ++k) sp[c * 12 + k] = dw_w[c * 9 + k] * sc;
        sp[c * 12 + 9]  = bn_beta[c] - bn_mean[c] * sc;
        sp[c * 12 + 10] = pw_w[c];
        sp[c * 12 + 11] = 0.f;
    }
    __syncthreads();

    const int h = blockIdx.x;
    const int b = blockIdx.y;
    const int w0 = tx * 4;
    const float* xb = x + ((size_t)b * C_) * (H_ * W_);

    float la0 = 0.f, la1 = 0.f, la2 = 0.f, la3 = 0.f;

    for (int cc = 0; cc < 24; ++cc) {
        const int c = ty * 24 + cc;
        const float4* pp = (const float4*)(sp + c * 12);
        const float4 p0 = pp[0];
        const float4 p1 = pp[1];
        const float4 p2 = pp[2];
        const float* xc = xb + c * (H_ * W_);

        float a0 = p2.y, a1 = p2.y, a2 = p2.y, a3 = p2.y;  // BN shift as init

        #pragma unroll
        for (int r = 0; r < 3; ++r) {
            const int hr = h + r - 1;
            float wk0, wk1, wk2;
            if (r == 0)      { wk0 = p0.x; wk1 = p0.y; wk2 = p0.z; }
            else if (r == 1) { wk0 = p0.w; wk1 = p1.x; wk2 = p1.y; }
            else             { wk0 = p1.z; wk1 = p1.w; wk2 = p2.x; }

            float win[6];
            if (hr >= 0 && hr < H_) {
                const float* row = xc + hr * W_ + w0;
                const float4 v = *(const float4*)row;
                win[0] = (tx > 0)  ? row[-1] : 0.f;
                win[1] = v.x; win[2] = v.y; win[3] = v.z; win[4] = v.w;
                win[5] = (tx < 23) ? row[4] : 0.f;
            } else {
                #pragma unroll
                for (int k = 0; k < 6; ++k) win[k] = 0.f;
            }
            a0 += wk0 * win[0] + wk1 * win[1] + wk2 * win[2];
            a1 += wk0 * win[1] + wk1 * win[2] + wk2 * win[3];
            a2 += wk0 * win[2] + wk1 * win[3] + wk2 * win[4];
            a3 += wk0 * win[3] + wk1 * win[4] + wk2 * win[5];
        }

        const float pw = p2.z;
        // fast SiLU: h/(1+e^-h) — error contribution to ranking ~1e-9, safe.
        la0 += __fdividef(a0, 1.0f + __expf(-a0)) * pw;
        la1 += __fdividef(a1, 1.0f + __expf(-a1)) * pw;
        la2 += __fdividef(a2, 1.0f + __expf(-a2)) * pw;
        la3 += __fdividef(a3, 1.0f + __expf(-a3)) * pw;
    }

    float4 lv; lv.x = la0; lv.y = la1; lv.z = la2; lv.w = la3;
    *(float4*)&spart[ty][w0] = lv;
    __syncthreads();

    if (tid < W_) {
        float s = 0.f;
        #pragma unroll
        for (int cg = 0; cg < 16; ++cg) s += spart[cg][tid];
        const float logit = s + pw_b[0];
        const float imp = 1.0f / (1.0f + expf(-logit));  // precise for ranking
        g_imp[(b * H_ + h) * W_ + tid] = imp;
    }
}

// ---------------------------------------------------------------------------
// Kernel B1: region scores = 4x4 block mean of importance. grid(B_), block(G_)
// ---------------------------------------------------------------------------
__global__ void scores_kernel()
{
    const int b = blockIdx.x;
    const int g = threadIdx.x;          // 0..575
    const int gh = g / GW_;
    const int gw = g - gh * GW_;
    const float4* ip = (const float4*)g_imp;
    float s = 0.f;
    #pragma unroll
    for (int rh = 0; rh < 4; ++rh) {
        const float4 v = ip[(b * H_ + gh * 4 + rh) * (W_ / 4) + gw];
        s += v.x + v.y + v.z + v.w;
    }
    g_scores[b * G_ + g] = s * (1.0f / 16.0f);
}

// ---------------------------------------------------------------------------
// Kernel B2: stable descending rank -> order. grid(9, B_), block(256).
// rank(g) = #{j: s_j > s_g} + #{j < g: s_j == s_g}; order[rank] = g.
// ---------------------------------------------------------------------------
__global__ void rank_kernel()
{
    __shared__ float ssc[G_];
    const int b = blockIdx.y;
    const int tid = threadIdx.x;
    for (int i = tid; i < G_; i += 256) ssc[i] = g_scores[b * G_ + i];
    __syncthreads();

    const int sub = tid & 3;
    const int g = blockIdx.x * 64 + (tid >> 2);
    const float sg = ssc[g];
    int cnt = 0;
    const int j0 = sub * 144;
    #pragma unroll 4
    for (int j = j0; j < j0 + 144; ++j) {
        const float sj = ssc[j];
        cnt += (sj > sg) || (sj == sg && j < g);
    }
    cnt += __shfl_xor_sync(0xFFFFFFFFu, cnt, 1);
    cnt += __shfl_xor_sync(0xFFFFFFFFu, cnt, 2);
    if (sub == 0) g_order[b * G_ + cnt] = g;
}

// ---------------------------------------------------------------------------
// Kernel C: smem-staged permute. One (b,c) image per block.
// Coalesced load (x + imp, modulated) -> smem scatter -> coalesced store.
// ---------------------------------------------------------------------------
__global__ __launch_bounds__(256)
void permute_kernel(const float* __restrict__ x,
                    const float* __restrict__ gs_p,
                    float* __restrict__ out)
{
    __shared__ float tile[H_][100];     // padded rows (100 floats) for bank spread
    __shared__ int   sorder[G_];

    const int tid = threadIdx.x;
    const int c = blockIdx.x;
    const int b = blockIdx.y;
    const float gs = __ldg(gs_p);

    for (int i = tid; i < G_; i += 256) sorder[i] = g_order[b * G_ + i];

    const size_t img = ((size_t)(b * C_ + c)) * (H_ * W_);
    const float4* xp = (const float4*)(x + img);
    const float4* ip = (const float4*)(g_imp + (size_t)b * (H_ * W_));

    #pragma unroll
    for (int k = 0; k < 9; ++k) {
        const int idx = tid + k * 256;      // 0..2303 float4s, coalesced
        const int hh = idx / 24;
        const int w4 = idx - hh * 24;
        const float4 v = xp[idx];
        const float4 im = ip[idx];
        float4 m;
        m.x = v.x * fmaf(gs, im.x, 1.0f);
        m.y = v.y * fmaf(gs, im.y, 1.0f);
        m.z = v.z * fmaf(gs, im.z, 1.0f);
        m.w = v.w * fmaf(gs, im.w, 1.0f);
        *(float4*)&tile[hh][w4 * 4] = m;
    }
    __syncthreads();

    float4* op = (float4*)(out + img);
    #pragma unroll
    for (int k = 0; k < 9; ++k) {
        const int idx = tid + k * 256;
        const int hh = idx / 24;
        const int w4 = idx - hh * 24;
        const int gh = hh >> 2;
        const int rh = hh & 3;
        const int src = sorder[gh * GW_ + w4];
        const int gh_s = src / GW_;
        const int gw_s = src - gh_s * GW_;
        const int h_s = gh_s * 4 + rh;
        op[idx] = *(const float4*)&tile[h_s][gw_s * 4];
    }
}

// ---------------------------------------------------------------------------
extern "C" void kernel_launch(void* const* d_in, const int* in_sizes, int n_in,
                              void* d_out, int out_size)
{
    const float* x        = (const float*)d_in[0];
    const float* dw_w     = (const float*)d_in[1];
    const float* bn_gamma = (const float*)d_in[2];
    const float* bn_beta  = (const float*)d_in[3];
    const float* bn_mean  = (const float*)d_in[4];
    const float* bn_var   = (const float*)d_in[5];
    const float* pw_w     = (const float*)d_in[6];
    const float* pw_b     = (const float*)d_in[7];
    const float* gs       = (const float*)d_in[8];
    float* out = (float*)d_out;

    importance_kernel<<<dim3(H_, B_), dim3(24, 16)>>>(
        x, dw_w, bn_gamma, bn_beta, bn_mean, bn_var, pw_w, pw_b);
    scores_kernel<<<B_, G_>>>();
    rank_kernel<<<dim3(9, B_), 256>>>();
    permute_kernel<<<dim3(C_, B_), 256>>>(x, gs, out);
}